// round 16
// baseline (speedup 1.0000x reference)
#include <cuda_runtime.h>
#include <cuda_bf16.h>
#include <cstdint>

// out[b,r] = sum_k Xa[b,k]*G[k,r] + C[r]   (Gaussian NB log-likelihood as GEMM)
//   Xa[b,k] = x[b,k] (k<512), x[b,k-512]^2 (k>=512), x = concat(sbjs, objs)
//   G[k,r]  = mu[r,k]/sig^2 (k<512), -0.5/sig^2 (k>=512)
//   C[r]    = sum_d(-0.5*mu^2/sig^2 - log sig) - 512*LOG_SQRT_2PI + 512*prior[r]
// TWO kernels:
//   nb_prep: bf16 B + C (absorbs first-kernel envelope/ramp)
//   nb_mma:  round-12 GEMM (BM64 x BN128, K-split x4 over x-cols, in-register
//            A conversion, B via cp.async) + in-kernel split-K combine: the
//            4th ks-partner per tile (atomic counter; no spin) sums the 4
//            fp32 partials + C in fixed order and stores out directly.

#define BATCH 4096
#define EMB   256
#define TWO_D 512
#define NREL  128
#define KDIM  1024
#define KSPLIT 4
#define NTILES (BATCH / 64)          // 64

#define ROWB    144                  // smem row pitch (64 halves + 8 pad)
#define A_CHUNK (64 * ROWB)          // 9216 B
#define B_CHUNK (128 * ROWB)         // 18432 B
#define A_ALL   (4 * A_CHUNK)        // 36864
#define SMEM_MMA (4 * A_CHUNK + 4 * B_CHUNK)   // 110592 B

__device__ __nv_bfloat16 g_B[NREL * KDIM];            // 256 KB (L2-resident)
__device__ float g_C[NREL];
__device__ float g_partial[KSPLIT * BATCH * NREL];    // 8 MB scratch
__device__ int   g_cnt[NTILES];                       // per-tile arrivals

__device__ __forceinline__ uint32_t smem_u32(const void* p) {
    uint32_t a;
    asm("{ .reg .u64 t; cvta.to.shared.u64 t, %1; cvt.u32.u64 %0, t; }"
        : "=r"(a) : "l"(p));
    return a;
}

#define LDSM4(r, addr) \
    asm volatile("ldmatrix.sync.aligned.m8n8.x4.shared.b16 {%0,%1,%2,%3}, [%4];" \
        : "=r"((r)[0]), "=r"((r)[1]), "=r"((r)[2]), "=r"((r)[3]) : "r"(addr))

__device__ __forceinline__ void mma16816(float* c, const uint32_t* a,
                                         uint32_t b0, uint32_t b1) {
    asm("mma.sync.aligned.m16n8k16.row.col.f32.bf16.bf16.f32 "
        "{%0,%1,%2,%3}, {%4,%5,%6,%7}, {%8,%9}, {%0,%1,%2,%3};"
        : "+f"(c[0]), "+f"(c[1]), "+f"(c[2]), "+f"(c[3])
        : "r"(a[0]), "r"(a[1]), "r"(a[2]), "r"(a[3]), "r"(b0), "r"(b1));
}

#define CP_ASYNC16(dst, src) \
    asm volatile("cp.async.cg.shared.global [%0], [%1], 16;" \
        :: "r"(dst), "l"(src) : "memory")
#define CP_COMMIT() asm volatile("cp.async.commit_group;" ::: "memory")

template <int N>
__device__ __forceinline__ void cp_waitg() {
    asm volatile("cp.async.wait_group %0;" :: "n"(N) : "memory");
}

#define STS16(addr, v) \
    asm volatile("st.shared.v4.b32 [%0], {%1,%2,%3,%4};" :: \
        "r"(addr), "r"((v).x), "r"((v).y), "r"((v).z), "r"((v).w))

__device__ __forceinline__ uint32_t bf2pack(float a, float b) {
    __nv_bfloat162 h = __float22bfloat162_rn(make_float2(a, b));
    return *reinterpret_cast<uint32_t*>(&h);
}

// ---------------------------------------------------------------------------
// Prep: bf16 B + C (prior folded). One CTA per relation.
// ---------------------------------------------------------------------------
__global__ void __launch_bounds__(256) nb_prep(
    const float* __restrict__ mus,
    const float* __restrict__ sigmas,
    const float* __restrict__ priors)
{
    const int r   = blockIdx.x;
    const int tid = threadIdx.x;
    __shared__ float red[8];

    float csum = 0.0f;
    #pragma unroll
    for (int j = 0; j < 2; j++) {
        int d = tid + 256 * j;
        float mu = mus[r * TWO_D + d];
        float s  = sigmas[r * TWO_D + d];
        float inv = 1.0f / (s * s);
        g_B[r * KDIM + d]         = __float2bfloat16_rn(mu * inv);
        g_B[r * KDIM + TWO_D + d] = __float2bfloat16_rn(-0.5f * inv);
        csum += fmaf(-0.5f * mu, mu * inv, -__logf(s));
    }
    #pragma unroll
    for (int o = 16; o > 0; o >>= 1)
        csum += __shfl_xor_sync(0xffffffffu, csum, o);
    if ((tid & 31) == 0) red[tid >> 5] = csum;
    __syncthreads();
    if (tid == 0) {
        float v = ((red[0] + red[1]) + (red[2] + red[3]))
                + ((red[4] + red[5]) + (red[6] + red[7]));
        g_C[r] = v - (float)TWO_D * 0.9189385332046727f
                   + priors[r] * (float)TWO_D;
    }
}

// ---------------------------------------------------------------------------
// GEMM. grid 256 = ks*64 + mt. CTA: BM=64 x BN=128, 4 K-chunks of 64:
// [lin p0, sq p0, lin p1, sq p1], pair p covers x-cols ks*128+p*64 .. +64.
// 8 warps (2x4), warp tile 32x32. 4th ks-partner combines and stores out.
// ---------------------------------------------------------------------------
struct MmaCtx {
    uint32_t aBase, bBase;
    float (*acc)[4][4];
};

template <int C>
__device__ __forceinline__ void mma_chunk(const MmaCtx& cx) {
    const uint32_t aA = cx.aBase + C * A_CHUNK;
    const uint32_t bA = cx.bBase + C * B_CHUNK;
    #pragma unroll
    for (int kk = 0; kk < 4; kk++) {
        uint32_t a0[4], a1[4], br0[4], br1[4];
        LDSM4(a0, aA + kk * 32);
        LDSM4(a1, aA + 16 * ROWB + kk * 32);
        LDSM4(br0, bA + kk * 32);
        LDSM4(br1, bA + 16 * ROWB + kk * 32);
        mma16816(cx.acc[0][0], a0, br0[0], br0[1]);
        mma16816(cx.acc[0][1], a0, br0[2], br0[3]);
        mma16816(cx.acc[0][2], a0, br1[0], br1[1]);
        mma16816(cx.acc[0][3], a0, br1[2], br1[3]);
        mma16816(cx.acc[1][0], a1, br0[0], br0[1]);
        mma16816(cx.acc[1][1], a1, br0[2], br0[3]);
        mma16816(cx.acc[1][2], a1, br1[0], br1[1]);
        mma16816(cx.acc[1][3], a1, br1[2], br1[3]);
    }
}

__global__ void __launch_bounds__(256, 2) nb_mma(
    const float* __restrict__ sbjs,
    const float* __restrict__ objs,
    const float* __restrict__ priors,
    float* __restrict__ out)
{
    extern __shared__ __align__(16) char sm[];
    __shared__ int s_fin;

    const int tid  = threadIdx.x;
    const int lane = tid & 31;
    const int wid  = tid >> 5;
    const int wm   = wid >> 2;
    const int wn   = wid & 3;
    const int bid  = blockIdx.x;
    const int mt   = bid & 63;
    const int ks   = bid >> 6;
    const int b0   = mt * 64;

    const uint32_t smb = smem_u32(sm);

    float acc[2][4][4];
    #pragma unroll
    for (int mi = 0; mi < 2; mi++)
        #pragma unroll
        for (int nf = 0; nf < 4; nf++)
            #pragma unroll
            for (int i = 0; i < 4; i++) acc[mi][nf][i] = 0.0f;

    // ---- front-batched fp32 X loads (MLP 8) ----
    const float* __restrict__ xsrc = (ks < 2) ? sbjs : objs;
    const int xb4  = (ks & 1) * 32;
    const int xrow = tid >> 2;
    const int xc4  = (tid & 3) * 4;
    float4 xv[2][4];
    {
        const float4* p = (const float4*)xsrc + (size_t)(b0 + xrow) * 64 + xb4 + xc4;
        #pragma unroll
        for (int j = 0; j < 4; j++) xv[0][j] = p[j];
        #pragma unroll
        for (int j = 0; j < 4; j++) xv[1][j] = p[16 + j];
    }

    // ---- B cp.async: pair groups (lin+sq chunks), 2 commits ----
    {
        #pragma unroll
        for (int p = 0; p < 2; p++) {
            const int klin = ks * 128 + p * 64;
            #pragma unroll
            for (int half = 0; half < 2; half++) {       // 0=lin, 1=sq
                const int kb = klin + half * TWO_D;
                const __nv_bfloat16* gb = g_B + kb;
                uint32_t db = smb + A_ALL + (2 * p + half) * B_CHUNK;
                #pragma unroll
                for (int j = 0; j < 4; j++) {
                    int i = tid + 256 * j;
                    int br = i >> 3, bs = i & 7;
                    CP_ASYNC16(db + br * ROWB + bs * 16,
                               gb + (size_t)br * KDIM + bs * 8);
                }
            }
            CP_COMMIT();
        }
    }

    // ---- convert + STS all 4 A chunks ----
    {
        const uint32_t abase = smb + xrow * ROWB + (tid & 3) * 32;
        #pragma unroll
        for (int p = 0; p < 2; p++) {
            float4 v0 = xv[p][0], v1 = xv[p][1], v2 = xv[p][2], v3 = xv[p][3];
            uint4 lA, lB, sA_, sB_;
            lA.x = bf2pack(v0.x, v0.y);  lA.y = bf2pack(v0.z, v0.w);
            lA.z = bf2pack(v1.x, v1.y);  lA.w = bf2pack(v1.z, v1.w);
            lB.x = bf2pack(v2.x, v2.y);  lB.y = bf2pack(v2.z, v2.w);
            lB.z = bf2pack(v3.x, v3.y);  lB.w = bf2pack(v3.z, v3.w);
            sA_.x = bf2pack(v0.x * v0.x, v0.y * v0.y);
            sA_.y = bf2pack(v0.z * v0.z, v0.w * v0.w);
            sA_.z = bf2pack(v1.x * v1.x, v1.y * v1.y);
            sA_.w = bf2pack(v1.z * v1.z, v1.w * v1.w);
            sB_.x = bf2pack(v2.x * v2.x, v2.y * v2.y);
            sB_.y = bf2pack(v2.z * v2.z, v2.w * v2.w);
            sB_.z = bf2pack(v3.x * v3.x, v3.y * v3.y);
            sB_.w = bf2pack(v3.z * v3.z, v3.w * v3.w);
            uint32_t aLin = abase + (2 * p) * A_CHUNK;
            uint32_t aSq  = abase + (2 * p + 1) * A_CHUNK;
            STS16(aLin, lA);
            STS16(aLin + 16, lB);
            STS16(aSq, sA_);
            STS16(aSq + 16, sB_);
        }
    }

    MmaCtx cx;
    cx.aBase = smb + (wm * 32 + (lane & 15)) * ROWB + (lane >> 4) * 16;
    cx.bBase = smb + A_ALL
             + (wn * 32 + (lane & 7) + ((lane >> 4) << 3)) * ROWB
             + ((lane >> 3) & 1) * 16;
    cx.acc = acc;

    cp_waitg<1>();
    __syncthreads();
    mma_chunk<0>(cx);
    mma_chunk<1>(cx);
    cp_waitg<0>();
    __syncthreads();
    mma_chunk<2>(cx);
    mma_chunk<3>(cx);

    // ---- write fp32 partial ----
    float* pout = g_partial + (size_t)ks * (BATCH * NREL);
    #pragma unroll
    for (int mi = 0; mi < 2; mi++) {
        const int r0 = b0 + wm * 32 + mi * 16 + (lane >> 2);
        #pragma unroll
        for (int nf = 0; nf < 4; nf++) {
            const float* a = acc[mi][nf];
            int col = wn * 32 + nf * 8 + (lane & 3) * 2;
            *(float2*)&pout[(size_t)r0 * NREL + col] =
                make_float2(a[0], a[1]);
            *(float2*)&pout[(size_t)(r0 + 8) * NREL + col] =
                make_float2(a[2], a[3]);
        }
    }
    __syncthreads();

    // ---- arrival count; 4th partner combines (no waiting needed) ----
    if (tid == 0) {
        __threadfence();
        int old = atomicAdd(&g_cnt[mt], 1);
        s_fin = (old == KSPLIT - 1) ? 1 : 0;
        if (old == KSPLIT - 1) g_cnt[mt] = 0;   // reset for next replay
    }
    __syncthreads();
    if (!s_fin) return;
    __threadfence();                             // see partners' partials

    // ---- Cs[r] into smem ----
    float* Cs = (float*)sm;
    if (tid < NREL) Cs[tid] = g_C[tid];
    __syncthreads();

    // ---- combine 4 partials + C -> out (fixed order = deterministic) ----
    {
        const int P = BATCH * NREL / 4;
        const float4* pp = (const float4*)g_partial + b0 * (NREL / 4);
        float4* po = (float4*)out + b0 * (NREL / 4);
        const float4* Cs4 = (const float4*)Cs;
        #pragma unroll
        for (int j = 0; j < 8; j++) {
            int f4 = tid + 256 * j;               // 0..2047
            float4 a = __ldcg(&pp[f4]);
            float4 b = __ldcg(&pp[f4 + P]);
            float4 c = __ldcg(&pp[f4 + 2 * P]);
            float4 d = __ldcg(&pp[f4 + 3 * P]);
            float4 C = Cs4[f4 & 31];
            float4 o;
            o.x = (a.x + b.x) + (c.x + d.x) + C.x;
            o.y = (a.y + b.y) + (c.y + d.y) + C.y;
            o.z = (a.z + b.z) + (c.z + d.z) + C.z;
            o.w = (a.w + b.w) + (c.w + d.w) + C.w;
            po[f4] = o;
        }
    }
}

extern "C" void kernel_launch(void* const* d_in, const int* in_sizes, int n_in,
                              void* d_out, int out_size)
{
    const float* sbjs   = (const float*)d_in[0];
    const float* objs   = (const float*)d_in[1];
    const float* mus    = (const float*)d_in[2];
    const float* sigmas = (const float*)d_in[3];
    const float* priors = (const float*)d_in[4];
    float* out = (float*)d_out;

    cudaFuncSetAttribute(nb_mma,
                         cudaFuncAttributeMaxDynamicSharedMemorySize, SMEM_MMA);

    nb_prep<<<NREL, 256>>>(mus, sigmas, priors);
    nb_mma<<<KSPLIT * NTILES, 256, SMEM_MMA>>>(sbjs, objs, priors, out);
}

// round 17
// speedup vs baseline: 1.0173x; 1.0173x over previous
#include <cuda_runtime.h>
#include <cuda_bf16.h>
#include <cstdint>

// out[b,r] = sum_k Xa[b,k]*G[k,r] + C[r]   (Gaussian NB log-likelihood as GEMM)
//   Xa[b,k] = x[b,k] (k<512), x[b,k-512]^2 (k>=512), x = concat(sbjs, objs)
//   G[k,r]  = mu[r,k]/sig^2 (k<512), -0.5/sig^2 (k>=512)
//   C[r]    = sum_d(-0.5*mu^2/sig^2 - log sig) - 512*LOG_SQRT_2PI + 512*prior[r]
// nb_prep:   bf16 B + C (absorbs first-kernel ramp)
// nb_mma:    BM64 x BN128 (full N), K-split x4 over x-columns, in-register A
//            conversion, B via cp.async, prefetch depth 4. ks=0 folds C into
//            its partial.
// nb_reduce: out = (p0+p1)+(p2+p3), 2 float4/thread, MLP-8 front-batched.

#define BATCH 4096
#define EMB   256
#define TWO_D 512
#define NREL  128
#define KDIM  1024
#define KSPLIT 4

#define ROWB    144                 // smem row pitch (64 halves + 8 pad)
#define A_CHUNK (64 * ROWB)         // 9216 B  (64 rows x 64 cols)
#define B_CHUNK (128 * ROWB)        // 18432 B (128 rows x 64 cols)
#define A_ALL   (4 * A_CHUNK)       // 36864
#define SMEM_MMA (4 * A_CHUNK + 4 * B_CHUNK)   // 110592 B

__device__ __nv_bfloat16 g_B[NREL * KDIM];            // 256 KB (L2-resident)
__device__ float g_C[NREL];
__device__ float g_partial[KSPLIT * BATCH * NREL];    // 8 MB scratch

__device__ __forceinline__ uint32_t smem_u32(const void* p) {
    uint32_t a;
    asm("{ .reg .u64 t; cvta.to.shared.u64 t, %1; cvt.u32.u64 %0, t; }"
        : "=r"(a) : "l"(p));
    return a;
}

#define LDSM4(r, addr) \
    asm volatile("ldmatrix.sync.aligned.m8n8.x4.shared.b16 {%0,%1,%2,%3}, [%4];" \
        : "=r"((r)[0]), "=r"((r)[1]), "=r"((r)[2]), "=r"((r)[3]) : "r"(addr))

__device__ __forceinline__ void mma16816(float* c, const uint32_t* a,
                                         uint32_t b0, uint32_t b1) {
    asm("mma.sync.aligned.m16n8k16.row.col.f32.bf16.bf16.f32 "
        "{%0,%1,%2,%3}, {%4,%5,%6,%7}, {%8,%9}, {%0,%1,%2,%3};"
        : "+f"(c[0]), "+f"(c[1]), "+f"(c[2]), "+f"(c[3])
        : "r"(a[0]), "r"(a[1]), "r"(a[2]), "r"(a[3]), "r"(b0), "r"(b1));
}

#define CP_ASYNC16(dst, src) \
    asm volatile("cp.async.cg.shared.global [%0], [%1], 16;" \
        :: "r"(dst), "l"(src) : "memory")
#define CP_COMMIT() asm volatile("cp.async.commit_group;" ::: "memory")

template <int N>
__device__ __forceinline__ void cp_waitg() {
    asm volatile("cp.async.wait_group %0;" :: "n"(N) : "memory");
}

#define STS16(addr, v) \
    asm volatile("st.shared.v4.b32 [%0], {%1,%2,%3,%4};" :: \
        "r"(addr), "r"((v).x), "r"((v).y), "r"((v).z), "r"((v).w))

__device__ __forceinline__ uint32_t bf2pack(float a, float b) {
    __nv_bfloat162 h = __float22bfloat162_rn(make_float2(a, b));
    return *reinterpret_cast<uint32_t*>(&h);
}

// ---------------------------------------------------------------------------
// Prep: bf16 B + C (prior folded). One CTA per relation.
// ---------------------------------------------------------------------------
__global__ void __launch_bounds__(256) nb_prep(
    const float* __restrict__ mus,
    const float* __restrict__ sigmas,
    const float* __restrict__ priors)
{
    const int r   = blockIdx.x;
    const int tid = threadIdx.x;
    __shared__ float red[8];

    float csum = 0.0f;
    #pragma unroll
    for (int j = 0; j < 2; j++) {
        int d = tid + 256 * j;
        float mu = mus[r * TWO_D + d];
        float s  = sigmas[r * TWO_D + d];
        float inv = 1.0f / (s * s);
        g_B[r * KDIM + d]         = __float2bfloat16_rn(mu * inv);
        g_B[r * KDIM + TWO_D + d] = __float2bfloat16_rn(-0.5f * inv);
        csum += fmaf(-0.5f * mu, mu * inv, -__logf(s));
    }
    #pragma unroll
    for (int o = 16; o > 0; o >>= 1)
        csum += __shfl_xor_sync(0xffffffffu, csum, o);
    if ((tid & 31) == 0) red[tid >> 5] = csum;
    __syncthreads();
    if (tid == 0) {
        float v = ((red[0] + red[1]) + (red[2] + red[3]))
                + ((red[4] + red[5]) + (red[6] + red[7]));
        g_C[r] = v - (float)TWO_D * 0.9189385332046727f
                   + priors[r] * (float)TWO_D;
    }
}

// ---------------------------------------------------------------------------
// GEMM. grid 256 = ks*64 + mt. CTA: BM=64 x BN=128, 4 K-chunks of 64:
// [lin p0, sq p0, lin p1, sq p1], pair p covers x-cols ks*128+p*64 .. +64.
// 8 warps (2x4), warp tile 32x32.
// ---------------------------------------------------------------------------
struct MmaCtx {
    uint32_t aBase, bBase;
    float (*acc)[4][4];
};

template <int C>
__device__ __forceinline__ void mma_chunk(const MmaCtx& cx) {
    const uint32_t aA = cx.aBase + C * A_CHUNK;
    const uint32_t bA = cx.bBase + C * B_CHUNK;
    #pragma unroll
    for (int kk = 0; kk < 4; kk++) {
        uint32_t a0[4], a1[4], br0[4], br1[4];
        LDSM4(a0, aA + kk * 32);
        LDSM4(a1, aA + 16 * ROWB + kk * 32);
        LDSM4(br0, bA + kk * 32);
        LDSM4(br1, bA + 16 * ROWB + kk * 32);
        mma16816(cx.acc[0][0], a0, br0[0], br0[1]);
        mma16816(cx.acc[0][1], a0, br0[2], br0[3]);
        mma16816(cx.acc[0][2], a0, br1[0], br1[1]);
        mma16816(cx.acc[0][3], a0, br1[2], br1[3]);
        mma16816(cx.acc[1][0], a1, br0[0], br0[1]);
        mma16816(cx.acc[1][1], a1, br0[2], br0[3]);
        mma16816(cx.acc[1][2], a1, br1[0], br1[1]);
        mma16816(cx.acc[1][3], a1, br1[2], br1[3]);
    }
}

__global__ void __launch_bounds__(256, 2) nb_mma(
    const float* __restrict__ sbjs,
    const float* __restrict__ objs)
{
    extern __shared__ __align__(16) char sm[];

    const int tid  = threadIdx.x;
    const int lane = tid & 31;
    const int wid  = tid >> 5;
    const int wm   = wid >> 2;
    const int wn   = wid & 3;
    const int bid  = blockIdx.x;
    const int mt   = bid & 63;
    const int ks   = bid >> 6;
    const int b0   = mt * 64;

    const uint32_t smb = smem_u32(sm);

    float acc[2][4][4];
    #pragma unroll
    for (int mi = 0; mi < 2; mi++)
        #pragma unroll
        for (int nf = 0; nf < 4; nf++)
            #pragma unroll
            for (int i = 0; i < 4; i++) acc[mi][nf][i] = 0.0f;

    // ---- front-batched fp32 X loads (MLP 8) ----
    const float* __restrict__ xsrc = (ks < 2) ? sbjs : objs;
    const int xb4  = (ks & 1) * 32;
    const int xrow = tid >> 2;
    const int xc4  = (tid & 3) * 4;
    float4 xv[2][4];
    {
        const float4* p = (const float4*)xsrc + (size_t)(b0 + xrow) * 64 + xb4 + xc4;
        #pragma unroll
        for (int j = 0; j < 4; j++) xv[0][j] = p[j];
        #pragma unroll
        for (int j = 0; j < 4; j++) xv[1][j] = p[16 + j];
    }

    // ---- B cp.async: pair groups (lin+sq chunks), 2 commits ----
    {
        #pragma unroll
        for (int p = 0; p < 2; p++) {
            const int klin = ks * 128 + p * 64;
            #pragma unroll
            for (int half = 0; half < 2; half++) {       // 0=lin, 1=sq
                const int kb = klin + half * TWO_D;
                const __nv_bfloat16* gb = g_B + kb;
                uint32_t db = smb + A_ALL + (2 * p + half) * B_CHUNK;
                #pragma unroll
                for (int j = 0; j < 4; j++) {
                    int i = tid + 256 * j;
                    int br = i >> 3, bs = i & 7;
                    CP_ASYNC16(db + br * ROWB + bs * 16,
                               gb + (size_t)br * KDIM + bs * 8);
                }
            }
            CP_COMMIT();
        }
    }

    // ---- convert + STS all 4 A chunks ----
    {
        const uint32_t abase = smb + xrow * ROWB + (tid & 3) * 32;
        #pragma unroll
        for (int p = 0; p < 2; p++) {
            float4 v0 = xv[p][0], v1 = xv[p][1], v2 = xv[p][2], v3 = xv[p][3];
            uint4 lA, lB, sA_, sB_;
            lA.x = bf2pack(v0.x, v0.y);  lA.y = bf2pack(v0.z, v0.w);
            lA.z = bf2pack(v1.x, v1.y);  lA.w = bf2pack(v1.z, v1.w);
            lB.x = bf2pack(v2.x, v2.y);  lB.y = bf2pack(v2.z, v2.w);
            lB.z = bf2pack(v3.x, v3.y);  lB.w = bf2pack(v3.z, v3.w);
            sA_.x = bf2pack(v0.x * v0.x, v0.y * v0.y);
            sA_.y = bf2pack(v0.z * v0.z, v0.w * v0.w);
            sA_.z = bf2pack(v1.x * v1.x, v1.y * v1.y);
            sA_.w = bf2pack(v1.z * v1.z, v1.w * v1.w);
            sB_.x = bf2pack(v2.x * v2.x, v2.y * v2.y);
            sB_.y = bf2pack(v2.z * v2.z, v2.w * v2.w);
            sB_.z = bf2pack(v3.x * v3.x, v3.y * v3.y);
            sB_.w = bf2pack(v3.z * v3.z, v3.w * v3.w);
            uint32_t aLin = abase + (2 * p) * A_CHUNK;
            uint32_t aSq  = abase + (2 * p + 1) * A_CHUNK;
            STS16(aLin, lA);
            STS16(aLin + 16, lB);
            STS16(aSq, sA_);
            STS16(aSq + 16, sB_);
        }
    }

    MmaCtx cx;
    cx.aBase = smb + (wm * 32 + (lane & 15)) * ROWB + (lane >> 4) * 16;
    cx.bBase = smb + A_ALL
             + (wn * 32 + (lane & 7) + ((lane >> 4) << 3)) * ROWB
             + ((lane >> 3) & 1) * 16;
    cx.acc = acc;

    cp_waitg<1>();
    __syncthreads();
    mma_chunk<0>(cx);
    mma_chunk<1>(cx);
    cp_waitg<0>();
    __syncthreads();
    mma_chunk<2>(cx);
    mma_chunk<3>(cx);

    // ---- epilogue: fp32 partials (ks=0 folds in C) ----
    float* pout = g_partial + (size_t)ks * (BATCH * NREL);
    #pragma unroll
    for (int mi = 0; mi < 2; mi++) {
        const int r0 = b0 + wm * 32 + mi * 16 + (lane >> 2);
        #pragma unroll
        for (int nf = 0; nf < 4; nf++) {
            const float* a = acc[mi][nf];
            int col = wn * 32 + nf * 8 + (lane & 3) * 2;
            float c0 = 0.0f, c1 = 0.0f;
            if (ks == 0) { c0 = g_C[col]; c1 = g_C[col + 1]; }
            *(float2*)&pout[(size_t)r0 * NREL + col] =
                make_float2(a[0] + c0, a[1] + c1);
            *(float2*)&pout[(size_t)(r0 + 8) * NREL + col] =
                make_float2(a[2] + c0, a[3] + c1);
        }
    }
}

// ---------------------------------------------------------------------------
// out = (p0+p1)+(p2+p3); C already in p0. 2 float4/thread, loads front-
// batched (MLP 8). Fixed order = deterministic.
// ---------------------------------------------------------------------------
__global__ void __launch_bounds__(256) nb_reduce(float* __restrict__ out)
{
    const int i0 = blockIdx.x * 512 + threadIdx.x;      // float4 index, out 0
    const int i1 = i0 + 256;                            // float4 index, out 1
    const int P  = BATCH * NREL / 4;
    const float4* p = (const float4*)g_partial;

    float4 a0 = __ldcg(&p[i0]);
    float4 b0 = __ldcg(&p[i0 + P]);
    float4 c0 = __ldcg(&p[i0 + 2 * P]);
    float4 d0 = __ldcg(&p[i0 + 3 * P]);
    float4 a1 = __ldcg(&p[i1]);
    float4 b1 = __ldcg(&p[i1 + P]);
    float4 c1 = __ldcg(&p[i1 + 2 * P]);
    float4 d1 = __ldcg(&p[i1 + 3 * P]);

    float4 o0, o1;
    o0.x = (a0.x + b0.x) + (c0.x + d0.x);
    o0.y = (a0.y + b0.y) + (c0.y + d0.y);
    o0.z = (a0.z + b0.z) + (c0.z + d0.z);
    o0.w = (a0.w + b0.w) + (c0.w + d0.w);
    o1.x = (a1.x + b1.x) + (c1.x + d1.x);
    o1.y = (a1.y + b1.y) + (c1.y + d1.y);
    o1.z = (a1.z + b1.z) + (c1.z + d1.z);
    o1.w = (a1.w + b1.w) + (c1.w + d1.w);
    ((float4*)out)[i0] = o0;
    ((float4*)out)[i1] = o1;
}

extern "C" void kernel_launch(void* const* d_in, const int* in_sizes, int n_in,
                              void* d_out, int out_size)
{
    const float* sbjs   = (const float*)d_in[0];
    const float* objs   = (const float*)d_in[1];
    const float* mus    = (const float*)d_in[2];
    const float* sigmas = (const float*)d_in[3];
    const float* priors = (const float*)d_in[4];
    float* out = (float*)d_out;

    cudaFuncSetAttribute(nb_mma,
                         cudaFuncAttributeMaxDynamicSharedMemorySize, SMEM_MMA);

    nb_prep<<<NREL, 256>>>(mus, sigmas, priors);
    nb_mma<<<KSPLIT * (BATCH / 64), 256, SMEM_MMA>>>(sbjs, objs);
    nb_reduce<<<(BATCH * NREL / 4) / 512, 256>>>(out);
}